// round 8
// baseline (speedup 1.0000x reference)
#include <cuda_runtime.h>
#include <cuda_bf16.h>
#include <math.h>
#include <stdint.h>

#define B_   4
#define T_   4096
#define C_   1024
#define H_   4096
#define E_   8
#define CAP_ 1024
#define G_   32
#define BK_  32
#define S_   40            // A smem row stride (elements), conflict-free
#define SB_  136           // B smem row stride (elements), conflict-free for LDSM.trans
#define NT_  512           // threads per GEMM CTA (16 warps, 4m x 4n grid)

// ======== scratch: EXACTLY round-1/5/6's set (proven) ========
__device__ float g_probs[B_ * E_ * T_];
__device__ float g_topp[G_ * CAP_];
__device__ int   g_topi[G_ * CAP_];
__device__ float g_h[(size_t)G_ * CAP_ * H_];     // 512 MB fp32 hidden acts

// ======== helpers ========
__device__ __forceinline__ uint32_t smem_u32(const void* p) {
    uint32_t a;
    asm("{ .reg .u64 t; cvta.to.shared.u64 t, %1; cvt.u32.u64 %0, t; }" : "=r"(a) : "l"(p));
    return a;
}
__device__ __forceinline__ void split_bf16(float v, __nv_bfloat16& h, __nv_bfloat16& l) {
    h = __float2bfloat16(v);
    l = __float2bfloat16(v - __bfloat162float(h));
}
__device__ __forceinline__ float gelu_f(float v) {
    return 0.5f * v * (1.0f + erff(v * 0.70710678118654752f));
}
__device__ __forceinline__ void mma16816(float* d, const uint32_t* a, const uint32_t* b) {
    asm volatile("mma.sync.aligned.m16n8k16.row.col.f32.bf16.bf16.f32 "
        "{%0,%1,%2,%3}, {%4,%5,%6,%7}, {%8,%9}, {%0,%1,%2,%3};"
        : "+f"(d[0]), "+f"(d[1]), "+f"(d[2]), "+f"(d[3])
        : "r"(a[0]), "r"(a[1]), "r"(a[2]), "r"(a[3]), "r"(b[0]), "r"(b[1]));
}
#define LDSM_X4(r, addr) \
    asm volatile("ldmatrix.sync.aligned.m8n8.x4.shared.b16 {%0,%1,%2,%3}, [%4];" \
        : "=r"((r)[0]), "=r"((r)[1]), "=r"((r)[2]), "=r"((r)[3]) : "r"(addr))
#define LDSM_X4_T(r, addr) \
    asm volatile("ldmatrix.sync.aligned.m8n8.x4.trans.shared.b16 {%0,%1,%2,%3}, [%4];" \
        : "=r"((r)[0]), "=r"((r)[1]), "=r"((r)[2]), "=r"((r)[3]) : "r"(addr))

// ======== gate + softmax (identical, proven) ========
__global__ __launch_bounds__(256) void gate_kernel(const float* __restrict__ x,
                                                   const float* __restrict__ gw) {
    __shared__ float sgw[E_][C_];
    for (int i = threadIdx.x; i < C_ * E_; i += 256) {
        int c = i >> 3, e = i & 7;
        sgw[e][c] = gw[i];
    }
    __syncthreads();
    const int warp = threadIdx.x >> 5, lane = threadIdx.x & 31;
    const int token = blockIdx.x * 8 + warp;
    const float* xrow = x + (size_t)token * C_;
    float acc[E_];
#pragma unroll
    for (int e = 0; e < E_; e++) acc[e] = 0.f;
    for (int c = lane; c < C_; c += 32) {
        float xv = xrow[c];
#pragma unroll
        for (int e = 0; e < E_; e++) acc[e] = fmaf(xv, sgw[e][c], acc[e]);
    }
#pragma unroll
    for (int off = 16; off > 0; off >>= 1)
#pragma unroll
        for (int e = 0; e < E_; e++) acc[e] += __shfl_xor_sync(0xffffffffu, acc[e], off);
    if (lane == 0) {
        float mx = acc[0];
#pragma unroll
        for (int e = 1; e < E_; e++) mx = fmaxf(mx, acc[e]);
        float s = 0.f, ex[E_];
#pragma unroll
        for (int e = 0; e < E_; e++) { ex[e] = expf(acc[e] - mx); s += ex[e]; }
        float inv = 1.0f / s;
        const int b = token >> 12, t = token & (T_ - 1);
#pragma unroll
        for (int e = 0; e < E_; e++)
            g_probs[((size_t)(b * E_ + e)) * T_ + t] = ex[e] * inv;
    }
}

// ======== top-k bitonic (identical, proven) ========
__global__ __launch_bounds__(1024) void topk_kernel() {
    __shared__ unsigned long long keys[T_];
    const int g = blockIdx.x;
    const float* p = g_probs + (size_t)g * T_;
    for (int i = threadIdx.x; i < T_; i += 1024) {
        unsigned pb = __float_as_uint(p[i]);
        keys[i] = ((unsigned long long)pb << 32) | (unsigned)(0xFFFFFFFFu - (unsigned)i);
    }
    __syncthreads();
    for (int k = 2; k <= T_; k <<= 1)
        for (int j = k >> 1; j > 0; j >>= 1) {
            for (int i = threadIdx.x; i < T_; i += 1024) {
                int ixj = i ^ j;
                if (ixj > i) {
                    unsigned long long a = keys[i], bb = keys[ixj];
                    bool dsc = ((i & k) == 0);
                    if (dsc ? (a < bb) : (a > bb)) { keys[i] = bb; keys[ixj] = a; }
                }
            }
            __syncthreads();
        }
    for (int i = threadIdx.x; i < CAP_; i += 1024) {
        unsigned long long kv = keys[i];
        g_topp[(size_t)g * CAP_ + i] = __uint_as_float((unsigned)(kv >> 32));
        g_topi[(size_t)g * CAP_ + i] = (int)(0xFFFFFFFFu - (unsigned)kv);
    }
}

// ======== MMA tile core: 512 threads, single buffer, reg prefetch (R6 structure) ========
// CTA 128x128, BK=32, 16 warps (4m x 4n), warp tile 32x32.
// A staged [m(128)][S_]: thread -> row tid&127, k-quarter (tid>>7)*8
// B staged [k(32)][SB_]: thread -> k-row tid&31, n-eighth (tid>>5)*8
__device__ __forceinline__ void mma_tile(
    const float* __restrict__ aRow,   // per-thread A ptr (row/kq applied)
    const float* __restrict__ bPos,   // per-thread B ptr (krow/nq applied)
    int nstride, int nkb,
    __nv_bfloat16* sAh, __nv_bfloat16* sAl,
    __nv_bfloat16* sBh, __nv_bfloat16* sBl,
    float acc[2][4][4])
{
    const int tid  = threadIdx.x;
    const int warp = tid >> 5, lane = tid & 31;
    const int m_off = (warp >> 2) * 32;
    const int n_off = (warp & 3) * 32;
    const int soA = (tid & 127) * S_ + (tid >> 7) * 8;
    const int soB = (tid & 31) * SB_ + (tid >> 5) * 8;

    const uint32_t uAh = smem_u32(sAh), uAl = smem_u32(sAl);
    const uint32_t uBh = smem_u32(sBh), uBl = smem_u32(sBl);
    const uint32_t aoff = (uint32_t)(((m_off + (lane & 15)) * S_ + ((lane & 16) ? 8 : 0)) * 2);
    const uint32_t boff = (uint32_t)(((lane & 15) * SB_ + n_off + ((lane & 16) ? 8 : 0)) * 2);

    float fa[8], fb[8];
    *(float4*)(fa)     = ((const float4*)aRow)[0];
    *(float4*)(fa + 4) = ((const float4*)aRow)[1];
    *(float4*)(fb)     = ((const float4*)bPos)[0];
    *(float4*)(fb + 4) = ((const float4*)bPos)[1];

    for (int kb = 0; kb < nkb; kb++) {
        // ---- convert + store this block (8 elems A, 8 elems B per thread) ----
        __align__(16) __nv_bfloat16 hb[8], lb[8];
#pragma unroll
        for (int j = 0; j < 8; j++) split_bf16(fa[j], hb[j], lb[j]);
        *(uint4*)(sAh + soA) = *(uint4*)hb;
        *(uint4*)(sAl + soA) = *(uint4*)lb;
#pragma unroll
        for (int j = 0; j < 8; j++) split_bf16(fb[j], hb[j], lb[j]);
        *(uint4*)(sBh + soB) = *(uint4*)hb;
        *(uint4*)(sBl + soB) = *(uint4*)lb;
        __syncthreads();

        if (kb + 1 < nkb) {
            const float* an = aRow + (size_t)(kb + 1) * BK_;
            const float* bn = bPos + (size_t)(kb + 1) * BK_ * nstride;
            *(float4*)(fa)     = ((const float4*)an)[0];
            *(float4*)(fa + 4) = ((const float4*)an)[1];
            *(float4*)(fb)     = ((const float4*)bn)[0];
            *(float4*)(fb + 4) = ((const float4*)bn)[1];
        }

#pragma unroll
        for (int ks = 0; ks < BK_; ks += 16) {
            uint32_t ah[2][4], al[2][4];
#pragma unroll
            for (int mt = 0; mt < 2; mt++) {
                const uint32_t aadd = aoff + (uint32_t)((mt * 16 * S_ + ks) * 2);
                LDSM_X4(ah[mt], uAh + aadd);
                LDSM_X4(al[mt], uAl + aadd);
            }
#pragma unroll
            for (int pair = 0; pair < 2; pair++) {
                uint32_t bh[4], bl[4];
                const uint32_t badd = boff + (uint32_t)((ks * SB_ + pair * 16) * 2);
                LDSM_X4_T(bh, uBh + badd);
                LDSM_X4_T(bl, uBl + badd);
#pragma unroll
                for (int sub = 0; sub < 2; sub++) {
                    const int nt = pair * 2 + sub;
#pragma unroll
                    for (int mt = 0; mt < 2; mt++) {
                        mma16816(acc[mt][nt], ah[mt], bh + 2 * sub);
                        mma16816(acc[mt][nt], ah[mt], bl + 2 * sub);
                        mma16816(acc[mt][nt], al[mt], bh + 2 * sub);
                    }
                }
            }
        }
        __syncthreads();
    }
}

// ======== GEMM1: g_h = gelu(gather(x) @ w1[e]), M=1024 N=4096 K=1024 ========
__global__ __launch_bounds__(NT_) void gemm1_mma(const float* __restrict__ x,
                                                 const float* __restrict__ w1) {
    __shared__ __align__(16) __nv_bfloat16 sAh[128 * S_], sAl[128 * S_];
    __shared__ __align__(16) __nv_bfloat16 sBh[BK_ * SB_], sBl[BK_ * SB_];
    __shared__ int s_row[128];

    const int tid = threadIdx.x;
    const int g = blockIdx.z, b = g >> 3, e = g & 7;
    const int m0 = blockIdx.y << 7, n0 = blockIdx.x << 7;
    if (tid < 128) s_row[tid] = g_topi[(size_t)g * CAP_ + m0 + tid];
    __syncthreads();

    const float* aRow = x + ((size_t)(b * T_ + s_row[tid & 127])) * C_ + (tid >> 7) * 8;
    const float* bPos = w1 + (size_t)e * C_ * H_ + (size_t)(tid & 31) * H_ + n0 + (tid >> 5) * 8;

    float acc[2][4][4];
#pragma unroll
    for (int mt = 0; mt < 2; mt++)
#pragma unroll
        for (int nt = 0; nt < 4; nt++)
#pragma unroll
            for (int i = 0; i < 4; i++) acc[mt][nt][i] = 0.f;

    mma_tile(aRow, bPos, H_, C_ / BK_, sAh, sAl, sBh, sBl, acc);

    const int warp = tid >> 5, lane = tid & 31;
    const int gq = lane >> 2, tq = lane & 3;
    const int m_off = (warp >> 2) * 32, n_off = (warp & 3) * 32;
#pragma unroll
    for (int mt = 0; mt < 2; mt++) {
        const int r0l = m_off + mt * 16 + gq;
#pragma unroll
        for (int nt = 0; nt < 4; nt++) {
            const int col = n0 + n_off + nt * 8 + tq * 2;
#pragma unroll
            for (int hrow = 0; hrow < 2; hrow++) {
                const int rl = r0l + hrow * 8;
                float2 v;
                v.x = gelu_f(acc[mt][nt][2 * hrow + 0]);
                v.y = gelu_f(acc[mt][nt][2 * hrow + 1]);
                *(float2*)(g_h + ((size_t)g * CAP_ + m0 + rl) * H_ + col) = v;
            }
        }
    }
}

// ======== GEMM2: out[b,tok] += p * (g_h @ w2[e]), M=1024 N=1024 K=4096 ========
__global__ __launch_bounds__(NT_) void gemm2_mma(const float* __restrict__ w2,
                                                 float* __restrict__ out) {
    __shared__ __align__(16) __nv_bfloat16 sAh[128 * S_], sAl[128 * S_];
    __shared__ __align__(16) __nv_bfloat16 sBh[BK_ * SB_], sBl[BK_ * SB_];
    __shared__ int   s_tok[128];
    __shared__ float s_p[128];

    const int tid = threadIdx.x;
    const int g = blockIdx.z, b = g >> 3, e = g & 7;
    const int m0 = blockIdx.y << 7, n0 = blockIdx.x << 7;
    if (tid < 128) {
        s_tok[tid] = g_topi[(size_t)g * CAP_ + m0 + tid];
        s_p[tid]   = g_topp[(size_t)g * CAP_ + m0 + tid];
    }
    __syncthreads();

    const float* aRow = g_h + ((size_t)g * CAP_ + m0 + (tid & 127)) * H_ + (tid >> 7) * 8;
    const float* bPos = w2 + (size_t)e * H_ * C_ + (size_t)(tid & 31) * C_ + n0 + (tid >> 5) * 8;

    float acc[2][4][4];
#pragma unroll
    for (int mt = 0; mt < 2; mt++)
#pragma unroll
        for (int nt = 0; nt < 4; nt++)
#pragma unroll
            for (int i = 0; i < 4; i++) acc[mt][nt][i] = 0.f;

    mma_tile(aRow, bPos, C_, H_ / BK_, sAh, sAl, sBh, sBl, acc);

    const int warp = tid >> 5, lane = tid & 31;
    const int gq = lane >> 2, tq = lane & 3;
    const int m_off = (warp >> 2) * 32, n_off = (warp & 3) * 32;
#pragma unroll
    for (int mt = 0; mt < 2; mt++) {
        const int r0l = m_off + mt * 16 + gq;
#pragma unroll
        for (int nt = 0; nt < 4; nt++) {
            const int col = n0 + n_off + nt * 8 + tq * 2;
#pragma unroll
            for (int hrow = 0; hrow < 2; hrow++) {
                const int rl = r0l + hrow * 8;
                const int tok = s_tok[rl];
                const float p = s_p[rl];
                float* orow = out + ((size_t)b * T_ + tok) * C_ + col;
                atomicAdd(orow,     acc[mt][nt][2 * hrow + 0] * p);
                atomicAdd(orow + 1, acc[mt][nt][2 * hrow + 1] * p);
            }
        }
    }
}

// ======== zero-init output ========
__global__ void zero_kernel(float4* __restrict__ out, int n4) {
    int i = blockIdx.x * blockDim.x + threadIdx.x;
    if (i < n4) out[i] = make_float4(0.f, 0.f, 0.f, 0.f);
}

// ======== launch ========
extern "C" void kernel_launch(void* const* d_in, const int* in_sizes, int n_in,
                              void* d_out, int out_size) {
    const float* x  = (const float*)d_in[0];
    const float* gw = (const float*)d_in[1];
    const float* w1 = (const float*)d_in[2];
    const float* w2 = (const float*)d_in[3];
    float* out = (float*)d_out;

    const int n4 = (B_ * T_ * C_) / 4;
    zero_kernel<<<(n4 + 255) / 256, 256>>>((float4*)out, n4);

    gate_kernel<<<(B_ * T_) / 8, 256>>>(x, gw);
    topk_kernel<<<G_, 1024>>>();

    gemm1_mma<<<dim3(H_ / 128, CAP_ / 128, G_), NT_>>>(x, w1);
    gemm2_mma<<<dim3(C_ / 128, CAP_ / 128, G_), NT_>>>(w2, out);
}

// round 10
// speedup vs baseline: 1.3085x; 1.3085x over previous
#include <cuda_runtime.h>
#include <cuda_bf16.h>
#include <math.h>
#include <stdint.h>

#define B_   4
#define T_   4096
#define C_   1024
#define H_   4096
#define E_   8
#define CAP_ 1024
#define G_   32
#define BK_  32
#define S_   40            // A smem row stride (elements)
#define SB_  264           // B smem row stride (elements), conflict-free (528B ≡ 16 mod 128)

// dynamic smem: Ah[128*S_] | Al | Bh[BK_*SB_] | Bl
#define ABUF_ (128 * S_)
#define BBUF_ (BK_ * SB_)
#define SMEM_BYTES_ ((2 * ABUF_ + 2 * BBUF_) * 2)   // 54272

// ======== scratch: proven set ========
__device__ float g_probs[B_ * E_ * T_];
__device__ float g_topp[G_ * CAP_];
__device__ int   g_topi[G_ * CAP_];
__device__ float g_h[(size_t)G_ * CAP_ * H_];

// ======== helpers ========
__device__ __forceinline__ uint32_t smem_u32(const void* p) {
    uint32_t a;
    asm("{ .reg .u64 t; cvta.to.shared.u64 t, %1; cvt.u32.u64 %0, t; }" : "=r"(a) : "l"(p));
    return a;
}
__device__ __forceinline__ void split_bf16(float v, __nv_bfloat16& h, __nv_bfloat16& l) {
    h = __float2bfloat16(v);
    l = __float2bfloat16(v - __bfloat162float(h));
}
__device__ __forceinline__ float gelu_f(float v) {
    return 0.5f * v * (1.0f + erff(v * 0.70710678118654752f));
}
__device__ __forceinline__ void mma16816(float* d, const uint32_t* a, const uint32_t* b) {
    asm volatile("mma.sync.aligned.m16n8k16.row.col.f32.bf16.bf16.f32 "
        "{%0,%1,%2,%3}, {%4,%5,%6,%7}, {%8,%9}, {%0,%1,%2,%3};"
        : "+f"(d[0]), "+f"(d[1]), "+f"(d[2]), "+f"(d[3])
        : "r"(a[0]), "r"(a[1]), "r"(a[2]), "r"(a[3]), "r"(b[0]), "r"(b[1]));
}
#define LDSM_X4(r, addr) \
    asm volatile("ldmatrix.sync.aligned.m8n8.x4.shared.b16 {%0,%1,%2,%3}, [%4];" \
        : "=r"((r)[0]), "=r"((r)[1]), "=r"((r)[2]), "=r"((r)[3]) : "r"(addr))
#define LDSM_X4_T(r, addr) \
    asm volatile("ldmatrix.sync.aligned.m8n8.x4.trans.shared.b16 {%0,%1,%2,%3}, [%4];" \
        : "=r"((r)[0]), "=r"((r)[1]), "=r"((r)[2]), "=r"((r)[3]) : "r"(addr))

// ======== gate + softmax (proven) ========
__global__ __launch_bounds__(256) void gate_kernel(const float* __restrict__ x,
                                                   const float* __restrict__ gw) {
    __shared__ float sgw[E_][C_];
    for (int i = threadIdx.x; i < C_ * E_; i += 256) {
        int c = i >> 3, e = i & 7;
        sgw[e][c] = gw[i];
    }
    __syncthreads();
    const int warp = threadIdx.x >> 5, lane = threadIdx.x & 31;
    const int token = blockIdx.x * 8 + warp;
    const float* xrow = x + (size_t)token * C_;
    float acc[E_];
#pragma unroll
    for (int e = 0; e < E_; e++) acc[e] = 0.f;
    for (int c = lane; c < C_; c += 32) {
        float xv = xrow[c];
#pragma unroll
        for (int e = 0; e < E_; e++) acc[e] = fmaf(xv, sgw[e][c], acc[e]);
    }
#pragma unroll
    for (int off = 16; off > 0; off >>= 1)
#pragma unroll
        for (int e = 0; e < E_; e++) acc[e] += __shfl_xor_sync(0xffffffffu, acc[e], off);
    if (lane == 0) {
        float mx = acc[0];
#pragma unroll
        for (int e = 1; e < E_; e++) mx = fmaxf(mx, acc[e]);
        float s = 0.f, ex[E_];
#pragma unroll
        for (int e = 0; e < E_; e++) { ex[e] = expf(acc[e] - mx); s += ex[e]; }
        float inv = 1.0f / s;
        const int b = token >> 12, t = token & (T_ - 1);
#pragma unroll
        for (int e = 0; e < E_; e++)
            g_probs[((size_t)(b * E_ + e)) * T_ + t] = ex[e] * inv;
    }
}

// ======== top-k bitonic (proven) ========
__global__ __launch_bounds__(1024) void topk_kernel() {
    __shared__ unsigned long long keys[T_];
    const int g = blockIdx.x;
    const float* p = g_probs + (size_t)g * T_;
    for (int i = threadIdx.x; i < T_; i += 1024) {
        unsigned pb = __float_as_uint(p[i]);
        keys[i] = ((unsigned long long)pb << 32) | (unsigned)(0xFFFFFFFFu - (unsigned)i);
    }
    __syncthreads();
    for (int k = 2; k <= T_; k <<= 1)
        for (int j = k >> 1; j > 0; j >>= 1) {
            for (int i = threadIdx.x; i < T_; i += 1024) {
                int ixj = i ^ j;
                if (ixj > i) {
                    unsigned long long a = keys[i], bb = keys[ixj];
                    bool dsc = ((i & k) == 0);
                    if (dsc ? (a < bb) : (a > bb)) { keys[i] = bb; keys[ixj] = a; }
                }
            }
            __syncthreads();
        }
    for (int i = threadIdx.x; i < CAP_; i += 1024) {
        unsigned long long kv = keys[i];
        g_topp[(size_t)g * CAP_ + i] = __uint_as_float((unsigned)(kv >> 32));
        g_topi[(size_t)g * CAP_ + i] = (int)(0xFFFFFFFFu - (unsigned)kv);
    }
}

// ======== MMA tile core: CTA 128x256, 8 warps (2m x 4n), warp tile 64x64 ========
// A staged [m(128)][S_]: thread -> row tid>>1, k-half (tid&1)*16  (R6 proven)
// B staged [k(32)][SB_]: thread -> k-row tid&31, 32 n at (tid>>5)*32 (conflict-free)
__device__ __forceinline__ void mma_tile(
    const float* __restrict__ aRow, const float* __restrict__ bPos,
    int nstride, int nkb, __nv_bfloat16* dsm, float acc[4][8][4])
{
    const int tid  = threadIdx.x;
    const int warp = tid >> 5, lane = tid & 31;
    const int m_off = (warp >> 2) * 64;
    const int n_off = (warp & 3) * 64;
    const int soA = (tid >> 1) * S_ + (tid & 1) * 16;
    const int soB = (tid & 31) * SB_ + (tid >> 5) * 32;

    __nv_bfloat16* sAh = dsm;
    __nv_bfloat16* sAl = dsm + ABUF_;
    __nv_bfloat16* sBh = dsm + 2 * ABUF_;
    __nv_bfloat16* sBl = dsm + 2 * ABUF_ + BBUF_;
    const uint32_t uAh = smem_u32(sAh), uAl = smem_u32(sAl);
    const uint32_t uBh = smem_u32(sBh), uBl = smem_u32(sBl);
    const uint32_t aoff = (uint32_t)(((m_off + (lane & 15)) * S_ + ((lane & 16) ? 8 : 0)) * 2);
    const uint32_t boff = (uint32_t)(((lane & 15) * SB_ + n_off + ((lane & 16) ? 8 : 0)) * 2);

    float fa[16], fb[32];
#pragma unroll
    for (int q = 0; q < 4; q++) *(float4*)(fa + 4 * q) = ((const float4*)aRow)[q];
#pragma unroll
    for (int q = 0; q < 8; q++) *(float4*)(fb + 4 * q) = ((const float4*)bPos)[q];

    for (int kb = 0; kb < nkb; kb++) {
        {   // ---- convert + store A (16 elems), B (32 elems) ----
            __align__(16) __nv_bfloat16 hb[16], lb[16];
#pragma unroll
            for (int j = 0; j < 16; j++) split_bf16(fa[j], hb[j], lb[j]);
            *(uint4*)(sAh + soA)     = ((uint4*)hb)[0];
            *(uint4*)(sAh + soA + 8) = ((uint4*)hb)[1];
            *(uint4*)(sAl + soA)     = ((uint4*)lb)[0];
            *(uint4*)(sAl + soA + 8) = ((uint4*)lb)[1];
#pragma unroll
            for (int j = 0; j < 16; j++) split_bf16(fb[j], hb[j], lb[j]);
            *(uint4*)(sBh + soB)     = ((uint4*)hb)[0];
            *(uint4*)(sBh + soB + 8) = ((uint4*)hb)[1];
            *(uint4*)(sBl + soB)     = ((uint4*)lb)[0];
            *(uint4*)(sBl + soB + 8) = ((uint4*)lb)[1];
#pragma unroll
            for (int j = 0; j < 16; j++) split_bf16(fb[16 + j], hb[j], lb[j]);
            *(uint4*)(sBh + soB + 16) = ((uint4*)hb)[0];
            *(uint4*)(sBh + soB + 24) = ((uint4*)hb)[1];
            *(uint4*)(sBl + soB + 16) = ((uint4*)lb)[0];
            *(uint4*)(sBl + soB + 24) = ((uint4*)lb)[1];
        }
        __syncthreads();

        if (kb + 1 < nkb) {
            const float* an = aRow + (size_t)(kb + 1) * BK_;
            const float* bn = bPos + (size_t)(kb + 1) * BK_ * nstride;
#pragma unroll
            for (int q = 0; q < 4; q++) *(float4*)(fa + 4 * q) = ((const float4*)an)[q];
#pragma unroll
            for (int q = 0; q < 8; q++) *(float4*)(fb + 4 * q) = ((const float4*)bn)[q];
        }

#pragma unroll
        for (int ks = 0; ks < BK_; ks += 16) {
            uint32_t ah[4][4], al[4][4];
#pragma unroll
            for (int mt = 0; mt < 4; mt++) {
                const uint32_t aadd = aoff + (uint32_t)((mt * 16 * S_ + ks) * 2);
                LDSM_X4(ah[mt], uAh + aadd);
                LDSM_X4(al[mt], uAl + aadd);
            }
#pragma unroll
            for (int pair = 0; pair < 4; pair++) {
                uint32_t bh[4], bl[4];
                const uint32_t badd = boff + (uint32_t)((ks * SB_ + pair * 16) * 2);
                LDSM_X4_T(bh, uBh + badd);
                LDSM_X4_T(bl, uBl + badd);
#pragma unroll
                for (int sub = 0; sub < 2; sub++) {
                    const int nt = pair * 2 + sub;
#pragma unroll
                    for (int mt = 0; mt < 4; mt++) {
                        mma16816(acc[mt][nt], ah[mt], bh + 2 * sub);
                        mma16816(acc[mt][nt], ah[mt], bl + 2 * sub);
                        mma16816(acc[mt][nt], al[mt], bh + 2 * sub);
                    }
                }
            }
        }
        __syncthreads();
    }
}

// ======== GEMM1: g_h = gelu(gather(x) @ w1[e]), CTA 128x256 ========
__global__ __launch_bounds__(256) void gemm1_mma(const float* __restrict__ x,
                                                 const float* __restrict__ w1) {
    extern __shared__ __align__(16) __nv_bfloat16 dsm[];
    __shared__ int s_row[128];

    const int tid = threadIdx.x;
    const int g = blockIdx.z, b = g >> 3, e = g & 7;
    const int m0 = blockIdx.y << 7, n0 = blockIdx.x << 8;
    if (tid < 128) s_row[tid] = g_topi[(size_t)g * CAP_ + m0 + tid];
    __syncthreads();

    const float* aRow = x + ((size_t)(b * T_ + s_row[tid >> 1])) * C_ + (tid & 1) * 16;
    const float* bPos = w1 + (size_t)e * C_ * H_ + (size_t)(tid & 31) * H_ + n0 + (tid >> 5) * 32;

    float acc[4][8][4];
#pragma unroll
    for (int mt = 0; mt < 4; mt++)
#pragma unroll
        for (int nt = 0; nt < 8; nt++)
#pragma unroll
            for (int i = 0; i < 4; i++) acc[mt][nt][i] = 0.f;

    mma_tile(aRow, bPos, H_, C_ / BK_, dsm, acc);

    const int warp = tid >> 5, lane = tid & 31;
    const int gq = lane >> 2, tq = lane & 3;
    const int m_off = (warp >> 2) * 64, n_off = (warp & 3) * 64;
#pragma unroll
    for (int mt = 0; mt < 4; mt++) {
        const int r0l = m_off + mt * 16 + gq;
#pragma unroll
        for (int nt = 0; nt < 8; nt++) {
            const int col = n0 + n_off + nt * 8 + tq * 2;
#pragma unroll
            for (int hrow = 0; hrow < 2; hrow++) {
                const int rl = r0l + hrow * 8;
                float2 v;
                v.x = gelu_f(acc[mt][nt][2 * hrow + 0]);
                v.y = gelu_f(acc[mt][nt][2 * hrow + 1]);
                *(float2*)(g_h + ((size_t)g * CAP_ + m0 + rl) * H_ + col) = v;
            }
        }
    }
}

// ======== GEMM2: out[b,tok] += p * (g_h @ w2[e]), CTA 128x256 ========
__global__ __launch_bounds__(256) void gemm2_mma(const float* __restrict__ w2,
                                                 float* __restrict__ out) {
    extern __shared__ __align__(16) __nv_bfloat16 dsm[];
    __shared__ int   s_tok[128];
    __shared__ float s_p[128];

    const int tid = threadIdx.x;
    const int g = blockIdx.z, b = g >> 3, e = g & 7;
    const int m0 = blockIdx.y << 7, n0 = blockIdx.x << 8;
    if (tid < 128) {
        s_tok[tid] = g_topi[(size_t)g * CAP_ + m0 + tid];
        s_p[tid]   = g_topp[(size_t)g * CAP_ + m0 + tid];
    }
    __syncthreads();

    const float* aRow = g_h + ((size_t)g * CAP_ + m0 + (tid >> 1)) * H_ + (tid & 1) * 16;
    const float* bPos = w2 + (size_t)e * H_ * C_ + (size_t)(tid & 31) * C_ + n0 + (tid >> 5) * 32;

    float acc[4][8][4];
#pragma unroll
    for (int mt = 0; mt < 4; mt++)
#pragma unroll
        for (int nt = 0; nt < 8; nt++)
#pragma unroll
            for (int i = 0; i < 4; i++) acc[mt][nt][i] = 0.f;

    mma_tile(aRow, bPos, C_, H_ / BK_, dsm, acc);

    const int warp = tid >> 5, lane = tid & 31;
    const int gq = lane >> 2, tq = lane & 3;
    const int m_off = (warp >> 2) * 64, n_off = (warp & 3) * 64;
#pragma unroll
    for (int mt = 0; mt < 4; mt++) {
        const int r0l = m_off + mt * 16 + gq;
#pragma unroll
        for (int nt = 0; nt < 8; nt++) {
            const int col = n0 + n_off + nt * 8 + tq * 2;
#pragma unroll
            for (int hrow = 0; hrow < 2; hrow++) {
                const int rl = r0l + hrow * 8;
                const int tok = s_tok[rl];
                const float p = s_p[rl];
                float* orow = out + ((size_t)b * T_ + tok) * C_ + col;
                atomicAdd(orow,     acc[mt][nt][2 * hrow + 0] * p);
                atomicAdd(orow + 1, acc[mt][nt][2 * hrow + 1] * p);
            }
        }
    }
}

// ======== zero-init output ========
__global__ void zero_kernel(float4* __restrict__ out, int n4) {
    int i = blockIdx.x * blockDim.x + threadIdx.x;
    if (i < n4) out[i] = make_float4(0.f, 0.f, 0.f, 0.f);
}

// ======== launch ========
extern "C" void kernel_launch(void* const* d_in, const int* in_sizes, int n_in,
                              void* d_out, int out_size) {
    const float* x  = (const float*)d_in[0];
    const float* gw = (const float*)d_in[1];
    const float* w1 = (const float*)d_in[2];
    const float* w2 = (const float*)d_in[3];
    float* out = (float*)d_out;

    cudaFuncSetAttribute(gemm1_mma, cudaFuncAttributeMaxDynamicSharedMemorySize, SMEM_BYTES_);
    cudaFuncSetAttribute(gemm2_mma, cudaFuncAttributeMaxDynamicSharedMemorySize, SMEM_BYTES_);

    const int n4 = (B_ * T_ * C_) / 4;
    zero_kernel<<<(n4 + 255) / 256, 256>>>((float4*)out, n4);

    gate_kernel<<<(B_ * T_) / 8, 256>>>(x, gw);
    topk_kernel<<<G_, 1024>>>();

    gemm1_mma<<<dim3(H_ / 256, CAP_ / 128, G_), 256, SMEM_BYTES_>>>(x, w1);
    gemm2_mma<<<dim3(C_ / 256, CAP_ / 128, G_), 256, SMEM_BYTES_>>>(w2, out);
}

// round 11
// speedup vs baseline: 1.7250x; 1.3183x over previous
#include <cuda_runtime.h>
#include <cuda_fp16.h>
#include <math.h>
#include <stdint.h>

#define B_   4
#define T_   4096
#define C_   1024
#define H_   4096
#define E_   8
#define CAP_ 1024
#define G_   32
#define BK_  32
#define S_   40            // A smem row stride (elements)
#define SB_  264           // B smem row stride (elements), conflict-free

// ======== scratch: proven set ========
__device__ float g_probs[B_ * E_ * T_];
__device__ float g_topp[G_ * CAP_];
__device__ int   g_topi[G_ * CAP_];
__device__ float g_h[(size_t)G_ * CAP_ * H_];

// ======== helpers ========
__device__ __forceinline__ uint32_t smem_u32(const void* p) {
    uint32_t a;
    asm("{ .reg .u64 t; cvta.to.shared.u64 t, %1; cvt.u32.u64 %0, t; }" : "=r"(a) : "l"(p));
    return a;
}
__device__ __forceinline__ float gelu_f(float v) {
    return 0.5f * v * (1.0f + erff(v * 0.70710678118654752f));
}
__device__ __forceinline__ void mma16816h(float* d, const uint32_t* a, const uint32_t* b) {
    asm volatile("mma.sync.aligned.m16n8k16.row.col.f32.f16.f16.f32 "
        "{%0,%1,%2,%3}, {%4,%5,%6,%7}, {%8,%9}, {%0,%1,%2,%3};"
        : "+f"(d[0]), "+f"(d[1]), "+f"(d[2]), "+f"(d[3])
        : "r"(a[0]), "r"(a[1]), "r"(a[2]), "r"(a[3]), "r"(b[0]), "r"(b[1]));
}
#define LDSM_X4(r, addr) \
    asm volatile("ldmatrix.sync.aligned.m8n8.x4.shared.b16 {%0,%1,%2,%3}, [%4];" \
        : "=r"((r)[0]), "=r"((r)[1]), "=r"((r)[2]), "=r"((r)[3]) : "r"(addr))
#define LDSM_X4_T(r, addr) \
    asm volatile("ldmatrix.sync.aligned.m8n8.x4.trans.shared.b16 {%0,%1,%2,%3}, [%4];" \
        : "=r"((r)[0]), "=r"((r)[1]), "=r"((r)[2]), "=r"((r)[3]) : "r"(addr))

// ======== gate + softmax (proven) ========
__global__ __launch_bounds__(256) void gate_kernel(const float* __restrict__ x,
                                                   const float* __restrict__ gw) {
    __shared__ float sgw[E_][C_];
    for (int i = threadIdx.x; i < C_ * E_; i += 256) {
        int c = i >> 3, e = i & 7;
        sgw[e][c] = gw[i];
    }
    __syncthreads();
    const int warp = threadIdx.x >> 5, lane = threadIdx.x & 31;
    const int token = blockIdx.x * 8 + warp;
    const float* xrow = x + (size_t)token * C_;
    float acc[E_];
#pragma unroll
    for (int e = 0; e < E_; e++) acc[e] = 0.f;
    for (int c = lane; c < C_; c += 32) {
        float xv = xrow[c];
#pragma unroll
        for (int e = 0; e < E_; e++) acc[e] = fmaf(xv, sgw[e][c], acc[e]);
    }
#pragma unroll
    for (int off = 16; off > 0; off >>= 1)
#pragma unroll
        for (int e = 0; e < E_; e++) acc[e] += __shfl_xor_sync(0xffffffffu, acc[e], off);
    if (lane == 0) {
        float mx = acc[0];
#pragma unroll
        for (int e = 1; e < E_; e++) mx = fmaxf(mx, acc[e]);
        float s = 0.f, ex[E_];
#pragma unroll
        for (int e = 0; e < E_; e++) { ex[e] = expf(acc[e] - mx); s += ex[e]; }
        float inv = 1.0f / s;
        const int b = token >> 12, t = token & (T_ - 1);
#pragma unroll
        for (int e = 0; e < E_; e++)
            g_probs[((size_t)(b * E_ + e)) * T_ + t] = ex[e] * inv;
    }
}

// ======== top-k bitonic (proven) ========
__global__ __launch_bounds__(1024) void topk_kernel() {
    __shared__ unsigned long long keys[T_];
    const int g = blockIdx.x;
    const float* p = g_probs + (size_t)g * T_;
    for (int i = threadIdx.x; i < T_; i += 1024) {
        unsigned pb = __float_as_uint(p[i]);
        keys[i] = ((unsigned long long)pb << 32) | (unsigned)(0xFFFFFFFFu - (unsigned)i);
    }
    __syncthreads();
    for (int k = 2; k <= T_; k <<= 1)
        for (int j = k >> 1; j > 0; j >>= 1) {
            for (int i = threadIdx.x; i < T_; i += 1024) {
                int ixj = i ^ j;
                if (ixj > i) {
                    unsigned long long a = keys[i], bb = keys[ixj];
                    bool dsc = ((i & k) == 0);
                    if (dsc ? (a < bb) : (a > bb)) { keys[i] = bb; keys[ixj] = a; }
                }
            }
            __syncthreads();
        }
    for (int i = threadIdx.x; i < CAP_; i += 1024) {
        unsigned long long kv = keys[i];
        g_topp[(size_t)g * CAP_ + i] = __uint_as_float((unsigned)(kv >> 32));
        g_topi[(size_t)g * CAP_ + i] = (int)(0xFFFFFFFFu - (unsigned)kv);
    }
}

// ======== MMA tile core: CTA 128x256, 8 warps (2m x 4n), warp tile 64x64, fp16 single-term ========
// A staged [m(128)][S_]: thread -> row tid>>1, k-half (tid&1)*16
// B staged [k(32)][SB_]: thread -> k-row tid&31, 32 n at (tid>>5)*32
__device__ __forceinline__ void mma_tile(
    const float* __restrict__ aRow, const float* __restrict__ bPos,
    int nstride, int nkb, __half* sA, __half* sB, float acc[4][8][4])
{
    const int tid  = threadIdx.x;
    const int warp = tid >> 5, lane = tid & 31;
    const int m_off = (warp >> 2) * 64;
    const int n_off = (warp & 3) * 64;
    const int soA = (tid >> 1) * S_ + (tid & 1) * 16;
    const int soB = (tid & 31) * SB_ + (tid >> 5) * 32;

    const uint32_t uA = smem_u32(sA), uB = smem_u32(sB);
    const uint32_t aoff = (uint32_t)(((m_off + (lane & 15)) * S_ + ((lane & 16) ? 8 : 0)) * 2);
    const uint32_t boff = (uint32_t)(((lane & 15) * SB_ + n_off + ((lane & 16) ? 8 : 0)) * 2);

    float fa[16], fb[32];
#pragma unroll
    for (int q = 0; q < 4; q++) *(float4*)(fa + 4 * q) = ((const float4*)aRow)[q];
#pragma unroll
    for (int q = 0; q < 8; q++) *(float4*)(fb + 4 * q) = ((const float4*)bPos)[q];

    for (int kb = 0; kb < nkb; kb++) {
        {   // ---- convert + store A (16), B (32) ----
            __align__(16) __half hv[16];
#pragma unroll
            for (int j = 0; j < 16; j++) hv[j] = __float2half(fa[j]);
            *(uint4*)(sA + soA)     = ((uint4*)hv)[0];
            *(uint4*)(sA + soA + 8) = ((uint4*)hv)[1];
#pragma unroll
            for (int j = 0; j < 16; j++) hv[j] = __float2half(fb[j]);
            *(uint4*)(sB + soB)     = ((uint4*)hv)[0];
            *(uint4*)(sB + soB + 8) = ((uint4*)hv)[1];
#pragma unroll
            for (int j = 0; j < 16; j++) hv[j] = __float2half(fb[16 + j]);
            *(uint4*)(sB + soB + 16) = ((uint4*)hv)[0];
            *(uint4*)(sB + soB + 24) = ((uint4*)hv)[1];
        }
        __syncthreads();

        if (kb + 1 < nkb) {
            const float* an = aRow + (size_t)(kb + 1) * BK_;
            const float* bn = bPos + (size_t)(kb + 1) * BK_ * nstride;
#pragma unroll
            for (int q = 0; q < 4; q++) *(float4*)(fa + 4 * q) = ((const float4*)an)[q];
#pragma unroll
            for (int q = 0; q < 8; q++) *(float4*)(fb + 4 * q) = ((const float4*)bn)[q];
        }

#pragma unroll
        for (int ks = 0; ks < BK_; ks += 16) {
            uint32_t ah[4][4];
#pragma unroll
            for (int mt = 0; mt < 4; mt++)
                LDSM_X4(ah[mt], uA + aoff + (uint32_t)((mt * 16 * S_ + ks) * 2));
#pragma unroll
            for (int pair = 0; pair < 4; pair++) {
                uint32_t bh[4];
                LDSM_X4_T(bh, uB + boff + (uint32_t)((ks * SB_ + pair * 16) * 2));
#pragma unroll
                for (int sub = 0; sub < 2; sub++) {
                    const int nt = pair * 2 + sub;
#pragma unroll
                    for (int mt = 0; mt < 4; mt++)
                        mma16816h(acc[mt][nt], ah[mt], bh + 2 * sub);
                }
            }
        }
        __syncthreads();
    }
}

// ======== GEMM1: g_h = gelu(gather(x) @ w1[e]), CTA 128x256 ========
__global__ __launch_bounds__(256) void gemm1_mma(const float* __restrict__ x,
                                                 const float* __restrict__ w1) {
    __shared__ __align__(16) __half sA[128 * S_];
    __shared__ __align__(16) __half sB[BK_ * SB_];
    __shared__ int s_row[128];

    const int tid = threadIdx.x;
    const int g = blockIdx.z, b = g >> 3, e = g & 7;
    const int m0 = blockIdx.y << 7, n0 = blockIdx.x << 8;
    if (tid < 128) s_row[tid] = g_topi[(size_t)g * CAP_ + m0 + tid];
    __syncthreads();

    const float* aRow = x + ((size_t)(b * T_ + s_row[tid >> 1])) * C_ + (tid & 1) * 16;
    const float* bPos = w1 + (size_t)e * C_ * H_ + (size_t)(tid & 31) * H_ + n0 + (tid >> 5) * 32;

    float acc[4][8][4];
#pragma unroll
    for (int mt = 0; mt < 4; mt++)
#pragma unroll
        for (int nt = 0; nt < 8; nt++)
#pragma unroll
            for (int i = 0; i < 4; i++) acc[mt][nt][i] = 0.f;

    mma_tile(aRow, bPos, H_, C_ / BK_, sA, sB, acc);

    const int warp = tid >> 5, lane = tid & 31;
    const int gq = lane >> 2, tq = lane & 3;
    const int m_off = (warp >> 2) * 64, n_off = (warp & 3) * 64;
#pragma unroll
    for (int mt = 0; mt < 4; mt++) {
        const int r0l = m_off + mt * 16 + gq;
#pragma unroll
        for (int nt = 0; nt < 8; nt++) {
            const int col = n0 + n_off + nt * 8 + tq * 2;
#pragma unroll
            for (int hrow = 0; hrow < 2; hrow++) {
                const int rl = r0l + hrow * 8;
                float2 v;
                v.x = gelu_f(acc[mt][nt][2 * hrow + 0]);
                v.y = gelu_f(acc[mt][nt][2 * hrow + 1]);
                *(float2*)(g_h + ((size_t)g * CAP_ + m0 + rl) * H_ + col) = v;
            }
        }
    }
}

// ======== GEMM2: out[b,tok] += p * (g_h @ w2[e]), CTA 128x256 ========
__global__ __launch_bounds__(256) void gemm2_mma(const float* __restrict__ w2,
                                                 float* __restrict__ out) {
    __shared__ __align__(16) __half sA[128 * S_];
    __shared__ __align__(16) __half sB[BK_ * SB_];
    __shared__ int   s_tok[128];
    __shared__ float s_p[128];

    const int tid = threadIdx.x;
    const int g = blockIdx.z, b = g >> 3, e = g & 7;
    const int m0 = blockIdx.y << 7, n0 = blockIdx.x << 8;
    if (tid < 128) {
        s_tok[tid] = g_topi[(size_t)g * CAP_ + m0 + tid];
        s_p[tid]   = g_topp[(size_t)g * CAP_ + m0 + tid];
    }
    __syncthreads();

    const float* aRow = g_h + ((size_t)g * CAP_ + m0 + (tid >> 1)) * H_ + (tid & 1) * 16;
    const float* bPos = w2 + (size_t)e * H_ * C_ + (size_t)(tid & 31) * C_ + n0 + (tid >> 5) * 32;

    float acc[4][8][4];
#pragma unroll
    for (int mt = 0; mt < 4; mt++)
#pragma unroll
        for (int nt = 0; nt < 8; nt++)
#pragma unroll
            for (int i = 0; i < 4; i++) acc[mt][nt][i] = 0.f;

    mma_tile(aRow, bPos, C_, H_ / BK_, sA, sB, acc);

    const int warp = tid >> 5, lane = tid & 31;
    const int gq = lane >> 2, tq = lane & 3;
    const int m_off = (warp >> 2) * 64, n_off = (warp & 3) * 64;
#pragma unroll
    for (int mt = 0; mt < 4; mt++) {
        const int r0l = m_off + mt * 16 + gq;
#pragma unroll
        for (int nt = 0; nt < 8; nt++) {
            const int col = n0 + n_off + nt * 8 + tq * 2;
#pragma unroll
            for (int hrow = 0; hrow < 2; hrow++) {
                const int rl = r0l + hrow * 8;
                const int tok = s_tok[rl];
                const float p = s_p[rl];
                float* orow = out + ((size_t)b * T_ + tok) * C_ + col;
                atomicAdd(orow,     acc[mt][nt][2 * hrow + 0] * p);
                atomicAdd(orow + 1, acc[mt][nt][2 * hrow + 1] * p);
            }
        }
    }
}

// ======== zero-init output ========
__global__ void zero_kernel(float4* __restrict__ out, int n4) {
    int i = blockIdx.x * blockDim.x + threadIdx.x;
    if (i < n4) out[i] = make_float4(0.f, 0.f, 0.f, 0.f);
}

// ======== launch ========
extern "C" void kernel_launch(void* const* d_in, const int* in_sizes, int n_in,
                              void* d_out, int out_size) {
    const float* x  = (const float*)d_in[0];
    const float* gw = (const float*)d_in[1];
    const float* w1 = (const float*)d_in[2];
    const float* w2 = (const float*)d_in[3];
    float* out = (float*)d_out;

    const int n4 = (B_ * T_ * C_) / 4;
    zero_kernel<<<(n4 + 255) / 256, 256>>>((float4*)out, n4);

    gate_kernel<<<(B_ * T_) / 8, 256>>>(x, gw);
    topk_kernel<<<G_, 1024>>>();

    gemm1_mma<<<dim3(H_ / 256, CAP_ / 128, G_), 256>>>(x, w1);
    gemm2_mma<<<dim3(C_ / 256, CAP_ / 128, G_), 256>>>(w2, out);
}

// round 14
// speedup vs baseline: 2.2713x; 1.3167x over previous
#include <cuda_runtime.h>
#include <cuda_fp16.h>
#include <math.h>
#include <stdint.h>

#define B_   4
#define T_   4096
#define C_   1024
#define H_   4096
#define E_   8
#define CAP_ 1024
#define G_   32
#define BK_  32
#define S_   40            // A smem row stride (elements)
#define SB_  264           // B smem row stride (elements), conflict-free

// ======== scratch: ALL 32-bit-typed symbols (16-bit data packed in uint32_t) ========
__device__ float    g_probs[B_ * E_ * T_];
__device__ float    g_topp[G_ * CAP_];
__device__ int      g_topi[G_ * CAP_];
__device__ uint32_t g_w1h[(size_t)E_ * C_ * H_ / 2];    //  64 MB w1 fp16 (packed)
__device__ uint32_t g_w2h[(size_t)E_ * H_ * C_ / 2];    //  64 MB w2 fp16 (packed)
__device__ uint32_t g_h16[(size_t)G_ * CAP_ * H_ / 2];  // 256 MB hidden acts fp16 (packed)

// ======== helpers ========
__device__ __forceinline__ uint32_t smem_u32(const void* p) {
    uint32_t a;
    asm("{ .reg .u64 t; cvta.to.shared.u64 t, %1; cvt.u32.u64 %0, t; }" : "=r"(a) : "l"(p));
    return a;
}
__device__ __forceinline__ float gelu_f(float v) {
    return 0.5f * v * (1.0f + erff(v * 0.70710678118654752f));
}
__device__ __forceinline__ void mma16816h(float* d, const uint32_t* a, const uint32_t* b) {
    asm volatile("mma.sync.aligned.m16n8k16.row.col.f32.f16.f16.f32 "
        "{%0,%1,%2,%3}, {%4,%5,%6,%7}, {%8,%9}, {%0,%1,%2,%3};"
        : "+f"(d[0]), "+f"(d[1]), "+f"(d[2]), "+f"(d[3])
        : "r"(a[0]), "r"(a[1]), "r"(a[2]), "r"(a[3]), "r"(b[0]), "r"(b[1]));
}
#define LDSM_X4(r, addr) \
    asm volatile("ldmatrix.sync.aligned.m8n8.x4.shared.b16 {%0,%1,%2,%3}, [%4];" \
        : "=r"((r)[0]), "=r"((r)[1]), "=r"((r)[2]), "=r"((r)[3]) : "r"(addr))
#define LDSM_X4_T(r, addr) \
    asm volatile("ldmatrix.sync.aligned.m8n8.x4.trans.shared.b16 {%0,%1,%2,%3}, [%4];" \
        : "=r"((r)[0]), "=r"((r)[1]), "=r"((r)[2]), "=r"((r)[3]) : "r"(addr))

// ======== gate + softmax + zero-init of out (fused; proven gate core) ========
__global__ __launch_bounds__(256) void gate_kernel(const float* __restrict__ x,
                                                   const float* __restrict__ gw,
                                                   float4* __restrict__ out4) {
    // zero d_out: 2048 blocks x 256 threads x 8 float4 = 16,777,216 floats
    {
        const int base = blockIdx.x * 256 + threadIdx.x;
        const float4 z = make_float4(0.f, 0.f, 0.f, 0.f);
#pragma unroll
        for (int q = 0; q < 8; q++) out4[base + q * 524288] = z;
    }
    __shared__ float sgw[E_][C_];
    for (int i = threadIdx.x; i < C_ * E_; i += 256) {
        int c = i >> 3, e = i & 7;
        sgw[e][c] = gw[i];
    }
    __syncthreads();
    const int warp = threadIdx.x >> 5, lane = threadIdx.x & 31;
    const int token = blockIdx.x * 8 + warp;
    const float* xrow = x + (size_t)token * C_;
    float acc[E_];
#pragma unroll
    for (int e = 0; e < E_; e++) acc[e] = 0.f;
    for (int c = lane; c < C_; c += 32) {
        float xv = xrow[c];
#pragma unroll
        for (int e = 0; e < E_; e++) acc[e] = fmaf(xv, sgw[e][c], acc[e]);
    }
#pragma unroll
    for (int off = 16; off > 0; off >>= 1)
#pragma unroll
        for (int e = 0; e < E_; e++) acc[e] += __shfl_xor_sync(0xffffffffu, acc[e], off);
    if (lane == 0) {
        float mx = acc[0];
#pragma unroll
        for (int e = 1; e < E_; e++) mx = fmaxf(mx, acc[e]);
        float s = 0.f, ex[E_];
#pragma unroll
        for (int e = 0; e < E_; e++) { ex[e] = expf(acc[e] - mx); s += ex[e]; }
        float inv = 1.0f / s;
        const int b = token >> 12, t = token & (T_ - 1);
#pragma unroll
        for (int e = 0; e < E_; e++)
            g_probs[((size_t)(b * E_ + e)) * T_ + t] = ex[e] * inv;
    }
}

// ======== top-k bitonic (proven) ========
__global__ __launch_bounds__(1024) void topk_kernel() {
    __shared__ unsigned long long keys[T_];
    const int g = blockIdx.x;
    const float* p = g_probs + (size_t)g * T_;
    for (int i = threadIdx.x; i < T_; i += 1024) {
        unsigned pb = __float_as_uint(p[i]);
        keys[i] = ((unsigned long long)pb << 32) | (unsigned)(0xFFFFFFFFu - (unsigned)i);
    }
    __syncthreads();
    for (int k = 2; k <= T_; k <<= 1)
        for (int j = k >> 1; j > 0; j >>= 1) {
            for (int i = threadIdx.x; i < T_; i += 1024) {
                int ixj = i ^ j;
                if (ixj > i) {
                    unsigned long long a = keys[i], bb = keys[ixj];
                    bool dsc = ((i & k) == 0);
                    if (dsc ? (a < bb) : (a > bb)) { keys[i] = bb; keys[ixj] = a; }
                }
            }
            __syncthreads();
        }
    for (int i = threadIdx.x; i < CAP_; i += 1024) {
        unsigned long long kv = keys[i];
        g_topp[(size_t)g * CAP_ + i] = __uint_as_float((unsigned)(kv >> 32));
        g_topi[(size_t)g * CAP_ + i] = (int)(0xFFFFFFFFu - (unsigned)kv);
    }
}

// ======== fp32 -> fp16 both weights in ONE launch (8 elems/thread) ========
__global__ __launch_bounds__(256) void convert_w(const float* __restrict__ w1,
                                                 const float* __restrict__ w2) {
    const int half_blocks = (E_ * C_ * H_) / (256 * 8);      // 16384
    const bool first = (blockIdx.x < half_blocks);
    const float* in = first ? w1 : w2;
    uint32_t* out = first ? g_w1h : g_w2h;
    const int bid = first ? blockIdx.x : (blockIdx.x - half_blocks);
    const size_t i = ((size_t)bid * 256 + threadIdx.x) * 8;
    float4 v0 = *(const float4*)(in + i);
    float4 v1 = *(const float4*)(in + i + 4);
    __align__(16) __half h[8];
    h[0] = __float2half(v0.x); h[1] = __float2half(v0.y);
    h[2] = __float2half(v0.z); h[3] = __float2half(v0.w);
    h[4] = __float2half(v1.x); h[5] = __float2half(v1.y);
    h[6] = __float2half(v1.z); h[7] = __float2half(v1.w);
    *(uint4*)(out + i / 2) = *(uint4*)h;
}

// ======== MMA tile core (R11-proven structure; fp16 B, fp32-or-fp16 A) ========
// CTA 128x256, BK=32, 8 warps (2m x 4n), warp tile 64x64. Single buffer, reg prefetch.
template <bool AF32>
__device__ __forceinline__ void mma_tile(
    const void* __restrict__ aPtr,
    const __half* __restrict__ bPos, int nstrideB,
    int nkb, __half* sA, __half* sB, float acc[4][8][4])
{
    const int tid  = threadIdx.x;
    const int warp = tid >> 5, lane = tid & 31;
    const int m_off = (warp >> 2) * 64;
    const int n_off = (warp & 3) * 64;
    const int soA = (tid >> 1) * S_ + (tid & 1) * 16;
    const int soB = (tid & 31) * SB_ + (tid >> 5) * 32;

    const uint32_t uA = smem_u32(sA), uB = smem_u32(sB);
    const uint32_t aoff = (uint32_t)(((m_off + (lane & 15)) * S_ + ((lane & 16) ? 8 : 0)) * 2);
    const uint32_t boff = (uint32_t)(((lane & 15) * SB_ + n_off + ((lane & 16) ? 8 : 0)) * 2);

    float fa[16];
    uint4 ha2[2];
    uint4 rb[4];
    if (AF32) {
        const float* ap = (const float*)aPtr;
#pragma unroll
        for (int q = 0; q < 4; q++) *(float4*)(fa + 4 * q) = ((const float4*)ap)[q];
    } else {
        const uint4* ap = (const uint4*)aPtr;
        ha2[0] = ap[0]; ha2[1] = ap[1];
    }
#pragma unroll
    for (int q = 0; q < 4; q++) rb[q] = ((const uint4*)bPos)[q];

    for (int kb = 0; kb < nkb; kb++) {
        if (AF32) {
            __align__(16) __half hv[16];
#pragma unroll
            for (int j = 0; j < 16; j++) hv[j] = __float2half(fa[j]);
            *(uint4*)(sA + soA)     = ((uint4*)hv)[0];
            *(uint4*)(sA + soA + 8) = ((uint4*)hv)[1];
        } else {
            *(uint4*)(sA + soA)     = ha2[0];
            *(uint4*)(sA + soA + 8) = ha2[1];
        }
        *(uint4*)(sB + soB)      = rb[0];
        *(uint4*)(sB + soB + 8)  = rb[1];
        *(uint4*)(sB + soB + 16) = rb[2];
        *(uint4*)(sB + soB + 24) = rb[3];
        __syncthreads();

        if (kb + 1 < nkb) {
            if (AF32) {
                const float* an = (const float*)aPtr + (size_t)(kb + 1) * BK_;
#pragma unroll
                for (int q = 0; q < 4; q++) *(float4*)(fa + 4 * q) = ((const float4*)an)[q];
            } else {
                const uint4* an = (const uint4*)((const __half*)aPtr + (size_t)(kb + 1) * BK_);
                ha2[0] = an[0]; ha2[1] = an[1];
            }
            const uint4* bn = (const uint4*)(bPos + (size_t)(kb + 1) * BK_ * nstrideB);
#pragma unroll
            for (int q = 0; q < 4; q++) rb[q] = bn[q];
        }

#pragma unroll
        for (int ks = 0; ks < BK_; ks += 16) {
            uint32_t ah[4][4];
#pragma unroll
            for (int mt = 0; mt < 4; mt++)
                LDSM_X4(ah[mt], uA + aoff + (uint32_t)((mt * 16 * S_ + ks) * 2));
#pragma unroll
            for (int pair = 0; pair < 4; pair++) {
                uint32_t bh[4];
                LDSM_X4_T(bh, uB + boff + (uint32_t)((ks * SB_ + pair * 16) * 2));
#pragma unroll
                for (int sub = 0; sub < 2; sub++) {
                    const int nt = pair * 2 + sub;
#pragma unroll
                    for (int mt = 0; mt < 4; mt++)
                        mma16816h(acc[mt][nt], ah[mt], bh + 2 * sub);
                }
            }
        }
        __syncthreads();
    }
}

// ======== GEMM1: g_h16 = gelu(gather(x) @ w1h[e]), CTA 128x256 ========
__global__ __launch_bounds__(256) void gemm1_mma(const float* __restrict__ x) {
    __shared__ __align__(16) __half sA[128 * S_];
    __shared__ __align__(16) __half sB[BK_ * SB_];
    __shared__ int s_row[128];

    const int tid = threadIdx.x;
    const int g = blockIdx.z, b = g >> 3, e = g & 7;
    const int m0 = blockIdx.y << 7, n0 = blockIdx.x << 8;
    if (tid < 128) s_row[tid] = g_topi[(size_t)g * CAP_ + m0 + tid];
    __syncthreads();

    const float* aRow = x + ((size_t)(b * T_ + s_row[tid >> 1])) * C_ + (tid & 1) * 16;
    const __half* bPos = (const __half*)g_w1h + (size_t)e * C_ * H_
                         + (size_t)(tid & 31) * H_ + n0 + (tid >> 5) * 32;

    float acc[4][8][4];
#pragma unroll
    for (int mt = 0; mt < 4; mt++)
#pragma unroll
        for (int nt = 0; nt < 8; nt++)
#pragma unroll
            for (int i = 0; i < 4; i++) acc[mt][nt][i] = 0.f;

    mma_tile<true>(aRow, bPos, H_, C_ / BK_, sA, sB, acc);

    const int warp = tid >> 5, lane = tid & 31;
    const int gq = lane >> 2, tq = lane & 3;
    const int m_off = (warp >> 2) * 64, n_off = (warp & 3) * 64;
#pragma unroll
    for (int mt = 0; mt < 4; mt++) {
        const int r0l = m_off + mt * 16 + gq;
#pragma unroll
        for (int nt = 0; nt < 8; nt++) {
            const int col = n0 + n_off + nt * 8 + tq * 2;
#pragma unroll
            for (int hrow = 0; hrow < 2; hrow++) {
                const int rl = r0l + hrow * 8;
                __half2 hv = __halves2half2(
                    __float2half(gelu_f(acc[mt][nt][2 * hrow + 0])),
                    __float2half(gelu_f(acc[mt][nt][2 * hrow + 1])));
                g_h16[((size_t)g * CAP_ + m0 + rl) * (H_ / 2) + (col >> 1)]
                    = *(uint32_t*)&hv;
            }
        }
    }
}

// ======== GEMM2: out[b,tok] += p * (g_h16 @ w2h[e]), CTA 128x256 ========
__global__ __launch_bounds__(256) void gemm2_mma(float* __restrict__ out) {
    __shared__ __align__(16) __half sA[128 * S_];
    __shared__ __align__(16) __half sB[BK_ * SB_];
    __shared__ int   s_tok[128];
    __shared__ float s_p[128];

    const int tid = threadIdx.x;
    const int g = blockIdx.z, b = g >> 3, e = g & 7;
    const int m0 = blockIdx.y << 7, n0 = blockIdx.x << 8;
    if (tid < 128) {
        s_tok[tid] = g_topi[(size_t)g * CAP_ + m0 + tid];
        s_p[tid]   = g_topp[(size_t)g * CAP_ + m0 + tid];
    }
    __syncthreads();

    const __half* aRow = (const __half*)g_h16 + ((size_t)g * CAP_ + m0 + (tid >> 1)) * H_
                         + (tid & 1) * 16;
    const __half* bPos = (const __half*)g_w2h + (size_t)e * H_ * C_
                         + (size_t)(tid & 31) * C_ + n0 + (tid >> 5) * 32;

    float acc[4][8][4];
#pragma unroll
    for (int mt = 0; mt < 4; mt++)
#pragma unroll
        for (int nt = 0; nt < 8; nt++)
#pragma unroll
            for (int i = 0; i < 4; i++) acc[mt][nt][i] = 0.f;

    mma_tile<false>(aRow, bPos, C_, H_ / BK_, sA, sB, acc);

    const int warp = tid >> 5, lane = tid & 31;
    const int gq = lane >> 2, tq = lane & 3;
    const int m_off = (warp >> 2) * 64, n_off = (warp & 3) * 64;
#pragma unroll
    for (int mt = 0; mt < 4; mt++) {
        const int r0l = m_off + mt * 16 + gq;
#pragma unroll
        for (int nt = 0; nt < 8; nt++) {
            const int col = n0 + n_off + nt * 8 + tq * 2;
#pragma unroll
            for (int hrow = 0; hrow < 2; hrow++) {
                const int rl = r0l + hrow * 8;
                const int tok = s_tok[rl];
                const float p = s_p[rl];
                float* orow = out + ((size_t)b * T_ + tok) * C_ + col;
                atomicAdd(orow,     acc[mt][nt][2 * hrow + 0] * p);
                atomicAdd(orow + 1, acc[mt][nt][2 * hrow + 1] * p);
            }
        }
    }
}

// ======== launch (exactly 5 kernels) ========
extern "C" void kernel_launch(void* const* d_in, const int* in_sizes, int n_in,
                              void* d_out, int out_size) {
    const float* x  = (const float*)d_in[0];
    const float* gw = (const float*)d_in[1];
    const float* w1 = (const float*)d_in[2];
    const float* w2 = (const float*)d_in[3];
    float* out = (float*)d_out;

    gate_kernel<<<(B_ * T_) / 8, 256>>>(x, gw, (float4*)out);
    topk_kernel<<<G_, 1024>>>();
    convert_w<<<2 * (E_ * C_ * H_) / (256 * 8), 256>>>(w1, w2);

    gemm1_mma<<<dim3(H_ / 256, CAP_ / 128, G_), 256>>>(x);
    gemm2_mma<<<dim3(C_ / 256, CAP_ / 128, G_), 256>>>(out);
}

// round 15
// speedup vs baseline: 3.3036x; 1.4545x over previous
#include <cuda_runtime.h>
#include <cuda_fp16.h>
#include <math.h>
#include <stdint.h>

#define B_   4
#define T_   4096
#define C_   1024
#define H_   4096
#define E_   8
#define CAP_ 1024
#define G_   32
#define BK_  32
#define S_   40            // A smem row stride (elements)
#define SB_  264           // B smem row stride (elements), conflict-free

#define ABUF_ (128 * S_)                   // 5120 elems
#define BBUF_ (BK_ * SB_)                  // 8448 elems
#define STG_  (ABUF_ + BBUF_)              // 13568 elems per stage
#define SMEM_BYTES_ (2 * STG_ * 2)         // 54272 B

// ======== scratch: ALL 32-bit-typed symbols; exactly 5 kernels (both constraints) ========
__device__ float    g_probs[B_ * E_ * T_];
__device__ float    g_topp[G_ * CAP_];
__device__ int      g_topi[G_ * CAP_];
__device__ uint32_t g_xg [(size_t)G_ * CAP_ * C_ / 2];  //  32 MB gathered tokens fp16
__device__ uint32_t g_w1h[(size_t)E_ * C_ * H_ / 2];    //  64 MB w1 fp16
__device__ uint32_t g_w2h[(size_t)E_ * H_ * C_ / 2];    //  64 MB w2 fp16
__device__ uint32_t g_h16[(size_t)G_ * CAP_ * H_ / 2];  // 256 MB hidden acts fp16

// ======== helpers ========
__device__ __forceinline__ uint32_t smem_u32(const void* p) {
    uint32_t a;
    asm("{ .reg .u64 t; cvta.to.shared.u64 t, %1; cvt.u32.u64 %0, t; }" : "=r"(a) : "l"(p));
    return a;
}
__device__ __forceinline__ float gelu_f(float v) {
    return 0.5f * v * (1.0f + erff(v * 0.70710678118654752f));
}
__device__ __forceinline__ void mma16816h(float* d, const uint32_t* a, const uint32_t* b) {
    asm volatile("mma.sync.aligned.m16n8k16.row.col.f32.f16.f16.f32 "
        "{%0,%1,%2,%3}, {%4,%5,%6,%7}, {%8,%9}, {%0,%1,%2,%3};"
        : "+f"(d[0]), "+f"(d[1]), "+f"(d[2]), "+f"(d[3])
        : "r"(a[0]), "r"(a[1]), "r"(a[2]), "r"(a[3]), "r"(b[0]), "r"(b[1]));
}
#define LDSM_X4(r, addr) \
    asm volatile("ldmatrix.sync.aligned.m8n8.x4.shared.b16 {%0,%1,%2,%3}, [%4];" \
        : "=r"((r)[0]), "=r"((r)[1]), "=r"((r)[2]), "=r"((r)[3]) : "r"(addr))
#define LDSM_X4_T(r, addr) \
    asm volatile("ldmatrix.sync.aligned.m8n8.x4.trans.shared.b16 {%0,%1,%2,%3}, [%4];" \
        : "=r"((r)[0]), "=r"((r)[1]), "=r"((r)[2]), "=r"((r)[3]) : "r"(addr))
#define CPA16(dst, src) \
    asm volatile("cp.async.cg.shared.global [%0], [%1], 16;" \
        :: "r"(dst), "l"(__cvta_generic_to_global(src)) : "memory")
#define CPA_COMMIT() asm volatile("cp.async.commit_group;" ::: "memory")
#define CPA_WAIT1()  asm volatile("cp.async.wait_group 1;" ::: "memory")
#define CPA_WAIT0()  asm volatile("cp.async.wait_group 0;" ::: "memory")

// ======== kernel 1: gate + softmax + zero-init out (proven R14) ========
__global__ __launch_bounds__(256) void gate_kernel(const float* __restrict__ x,
                                                   const float* __restrict__ gw,
                                                   float4* __restrict__ out4) {
    {
        const int base = blockIdx.x * 256 + threadIdx.x;
        const float4 z = make_float4(0.f, 0.f, 0.f, 0.f);
#pragma unroll
        for (int q = 0; q < 8; q++) out4[base + q * 524288] = z;
    }
    __shared__ float sgw[E_][C_];
    for (int i = threadIdx.x; i < C_ * E_; i += 256) {
        int c = i >> 3, e = i & 7;
        sgw[e][c] = gw[i];
    }
    __syncthreads();
    const int warp = threadIdx.x >> 5, lane = threadIdx.x & 31;
    const int token = blockIdx.x * 8 + warp;
    const float* xrow = x + (size_t)token * C_;
    float acc[E_];
#pragma unroll
    for (int e = 0; e < E_; e++) acc[e] = 0.f;
    for (int c = lane; c < C_; c += 32) {
        float xv = xrow[c];
#pragma unroll
        for (int e = 0; e < E_; e++) acc[e] = fmaf(xv, sgw[e][c], acc[e]);
    }
#pragma unroll
    for (int off = 16; off > 0; off >>= 1)
#pragma unroll
        for (int e = 0; e < E_; e++) acc[e] += __shfl_xor_sync(0xffffffffu, acc[e], off);
    if (lane == 0) {
        float mx = acc[0];
#pragma unroll
        for (int e = 1; e < E_; e++) mx = fmaxf(mx, acc[e]);
        float s = 0.f, ex[E_];
#pragma unroll
        for (int e = 0; e < E_; e++) { ex[e] = expf(acc[e] - mx); s += ex[e]; }
        float inv = 1.0f / s;
        const int b = token >> 12, t = token & (T_ - 1);
#pragma unroll
        for (int e = 0; e < E_; e++)
            g_probs[((size_t)(b * E_ + e)) * T_ + t] = ex[e] * inv;
    }
}

// ======== kernel 2: top-k bitonic (proven) ========
__global__ __launch_bounds__(1024) void topk_kernel() {
    __shared__ unsigned long long keys[T_];
    const int g = blockIdx.x;
    const float* p = g_probs + (size_t)g * T_;
    for (int i = threadIdx.x; i < T_; i += 1024) {
        unsigned pb = __float_as_uint(p[i]);
        keys[i] = ((unsigned long long)pb << 32) | (unsigned)(0xFFFFFFFFu - (unsigned)i);
    }
    __syncthreads();
    for (int k = 2; k <= T_; k <<= 1)
        for (int j = k >> 1; j > 0; j >>= 1) {
            for (int i = threadIdx.x; i < T_; i += 1024) {
                int ixj = i ^ j;
                if (ixj > i) {
                    unsigned long long a = keys[i], bb = keys[ixj];
                    bool dsc = ((i & k) == 0);
                    if (dsc ? (a < bb) : (a > bb)) { keys[i] = bb; keys[ixj] = a; }
                }
            }
            __syncthreads();
        }
    for (int i = threadIdx.x; i < CAP_; i += 1024) {
        unsigned long long kv = keys[i];
        g_topp[(size_t)g * CAP_ + i] = __uint_as_float((unsigned)(kv >> 32));
        g_topi[(size_t)g * CAP_ + i] = (int)(0xFFFFFFFFu - (unsigned)kv);
    }
}

// ======== kernel 3: prep = w1 convert | w2 convert | gather+convert x ========
// blocks [0,16384): w1 ; [16384,32768): w2 ; [32768,49152): gather (2 rows/block)
__global__ __launch_bounds__(256) void prep_kernel(const float* __restrict__ x,
                                                   const float* __restrict__ w1,
                                                   const float* __restrict__ w2) {
    const int WB = (E_ * C_ * H_) / (256 * 8);      // 16384
    const int tid = threadIdx.x;
    if (blockIdx.x < 2 * WB) {
        const bool first = (blockIdx.x < WB);
        const float* in = first ? w1 : w2;
        uint32_t* out = first ? g_w1h : g_w2h;
        const int bid = first ? blockIdx.x : (blockIdx.x - WB);
        const size_t i = ((size_t)bid * 256 + tid) * 8;
        float4 v0 = *(const float4*)(in + i);
        float4 v1 = *(const float4*)(in + i + 4);
        __align__(16) __half h[8];
        h[0] = __float2half(v0.x); h[1] = __float2half(v0.y);
        h[2] = __float2half(v0.z); h[3] = __float2half(v0.w);
        h[4] = __float2half(v1.x); h[5] = __float2half(v1.y);
        h[6] = __float2half(v1.z); h[7] = __float2half(v1.w);
        *(uint4*)(out + i / 2) = *(uint4*)h;
    } else {
        const int gi = (blockIdx.x - 2 * WB) * 2 + (tid >> 7);   // gathered row
        const int g = gi >> 10, b = g >> 3;
        const int tok = g_topi[gi];
        const int t = tid & 127;
        const float4* src = (const float4*)(x + ((size_t)(b * T_ + tok)) * C_) + 2 * t;
        float4 v0 = src[0], v1 = src[1];
        __align__(16) __half h[8];
        h[0] = __float2half(v0.x); h[1] = __float2half(v0.y);
        h[2] = __float2half(v0.z); h[3] = __float2half(v0.w);
        h[4] = __float2half(v1.x); h[5] = __float2half(v1.y);
        h[6] = __float2half(v1.z); h[7] = __float2half(v1.w);
        *(uint4*)(g_xg + (size_t)gi * (C_ / 2) + t * 4) = *(uint4*)h;
    }
}

// ======== MMA tile core: cp.async double-buffered, all-fp16 operands ========
// CTA 128x256, BK=32, 8 warps (2m x 4n), warp tile 64x64.
__device__ __forceinline__ void mma_tile(
    const __half* __restrict__ gA, int kstrideA,
    const __half* __restrict__ gB, int kstrideB,
    int nkb, __half* dsm, float acc[4][8][4])
{
    const int tid  = threadIdx.x;
    const int warp = tid >> 5, lane = tid & 31;
    const int m_off = (warp >> 2) * 64;
    const int n_off = (warp & 3) * 64;

    const int rA = tid >> 2, kcA = (tid & 3) * 8;          // A: rows rA, rA+64
    const int krB = tid >> 5, ncB = (tid & 31) * 8;        // B: k-rows krB+8q
    const __half* srcA0 = gA + (size_t)rA * kstrideA + kcA;
    const __half* srcA1 = gA + (size_t)(rA + 64) * kstrideA + kcA;
    const __half* srcB  = gB + (size_t)krB * kstrideB + ncB;
    const uint32_t ub = smem_u32(dsm);
    const uint32_t dA0 = (uint32_t)((rA * S_ + kcA) * 2);
    const uint32_t dA1 = dA0 + (uint32_t)(64 * S_ * 2);
    const uint32_t dB  = (uint32_t)((krB * SB_ + ncB) * 2 + ABUF_ * 2);

    const uint32_t aoff = (uint32_t)(((m_off + (lane & 15)) * S_ + ((lane & 16) ? 8 : 0)) * 2);
    const uint32_t boff = (uint32_t)(((lane & 15) * SB_ + n_off + ((lane & 16) ? 8 : 0)) * 2 + ABUF_ * 2);

#define ISSUE_STAGE(s, kb) do {                                                       \
    const uint32_t _sb = ub + (uint32_t)(s) * (STG_ * 2);                             \
    const size_t _ka = (size_t)(kb) * BK_;                                            \
    CPA16(_sb + dA0, srcA0 + _ka);                                                    \
    CPA16(_sb + dA1, srcA1 + _ka);                                                    \
    const size_t _kb2 = (size_t)(kb) * BK_ * kstrideB;                                \
    CPA16(_sb + dB,                            srcB + _kb2);                          \
    CPA16(_sb + dB + (uint32_t)(8  * SB_ * 2), srcB + _kb2 + (size_t)8  * kstrideB);  \
    CPA16(_sb + dB + (uint32_t)(16 * SB_ * 2), srcB + _kb2 + (size_t)16 * kstrideB);  \
    CPA16(_sb + dB + (uint32_t)(24 * SB_ * 2), srcB + _kb2 + (size_t)24 * kstrideB);  \
    CPA_COMMIT();                                                                     \
} while (0)

    ISSUE_STAGE(0, 0);

    for (int kb = 0; kb < nkb; kb++) {
        const int s = kb & 1;
        if (kb + 1 < nkb) { ISSUE_STAGE(s ^ 1, kb + 1); CPA_WAIT1(); }
        else              { CPA_WAIT0(); }
        __syncthreads();

        const uint32_t sbase = ub + (uint32_t)s * (STG_ * 2);
#pragma unroll
        for (int ks = 0; ks < BK_; ks += 16) {
            uint32_t ah[4][4];
#pragma unroll
            for (int mt = 0; mt < 4; mt++)
                LDSM_X4(ah[mt], sbase + aoff + (uint32_t)((mt * 16 * S_ + ks) * 2));
#pragma unroll
            for (int pair = 0; pair < 4; pair++) {
                uint32_t bh[4];
                LDSM_X4_T(bh, sbase + boff + (uint32_t)((ks * SB_ + pair * 16) * 2));
#pragma unroll
                for (int sub = 0; sub < 2; sub++) {
                    const int nt = pair * 2 + sub;
#pragma unroll
                    for (int mt = 0; mt < 4; mt++)
                        mma16816h(acc[mt][nt], ah[mt], bh + 2 * sub);
                }
            }
        }
        __syncthreads();
    }
#undef ISSUE_STAGE
}

// ======== kernel 4: GEMM1 = gelu(xg @ w1h[e]) -> g_h16, CTA 128x256 ========
__global__ __launch_bounds__(256) void gemm1_mma() {
    extern __shared__ __align__(16) __half dsm[];
    const int tid = threadIdx.x;
    const int g = blockIdx.z, e = g & 7;
    const int m0 = blockIdx.y << 7, n0 = blockIdx.x << 8;

    float acc[4][8][4];
#pragma unroll
    for (int mt = 0; mt < 4; mt++)
#pragma unroll
        for (int nt = 0; nt < 8; nt++)
#pragma unroll
            for (int i = 0; i < 4; i++) acc[mt][nt][i] = 0.f;

    mma_tile((const __half*)g_xg + ((size_t)g * CAP_ + m0) * C_, C_,
             (const __half*)g_w1h + (size_t)e * C_ * H_ + n0, H_,
             C_ / BK_, dsm, acc);

    const int warp = tid >> 5, lane = tid & 31;
    const int gq = lane >> 2, tq = lane & 3;
    const int m_off = (warp >> 2) * 64, n_off = (warp & 3) * 64;
#pragma unroll
    for (int mt = 0; mt < 4; mt++) {
        const int r0l = m_off + mt * 16 + gq;
#pragma unroll
        for (int nt = 0; nt < 8; nt++) {
            const int col = n0 + n_off + nt * 8 + tq * 2;
#pragma unroll
            for (int hrow = 0; hrow < 2; hrow++) {
                const int rl = r0l + hrow * 8;
                __half2 hv = __halves2half2(
                    __float2half(gelu_f(acc[mt][nt][2 * hrow + 0])),
                    __float2half(gelu_f(acc[mt][nt][2 * hrow + 1])));
                g_h16[((size_t)g * CAP_ + m0 + rl) * (H_ / 2) + (col >> 1)]
                    = *(uint32_t*)&hv;
            }
        }
    }
}

// ======== kernel 5: GEMM2 = scatter(p * (g_h16 @ w2h[e])), CTA 128x256 ========
__global__ __launch_bounds__(256) void gemm2_mma(float* __restrict__ out) {
    extern __shared__ __align__(16) __half dsm[];
    __shared__ int   s_tok[128];
    __shared__ float s_p[128];

    const int tid = threadIdx.x;
    const int g = blockIdx.z, b = g >> 3, e = g & 7;
    const int m0 = blockIdx.y << 7, n0 = blockIdx.x << 8;
    if (tid < 128) {
        s_tok[tid] = g_topi[(size_t)g * CAP_ + m0 + tid];
        s_p[tid]   = g_topp[(size_t)g * CAP_ + m0 + tid];
    }
    __syncthreads();

    float acc[4][8][4];
#pragma unroll
    for (int mt = 0; mt < 4; mt++)
#pragma unroll
        for (int nt = 0; nt < 8; nt++)
#pragma unroll
            for (int i = 0; i < 4; i++) acc[mt][nt][i] = 0.f;

    mma_tile((const __half*)g_h16 + ((size_t)g * CAP_ + m0) * H_, H_,
             (const __half*)g_w2h + (size_t)e * H_ * C_ + n0, C_,
             H_ / BK_, dsm, acc);

    const int warp = tid >> 5, lane = tid & 31;
    const int gq = lane >> 2, tq = lane & 3;
    const int m_off = (warp >> 2) * 64, n_off = (warp & 3) * 64;
#pragma unroll
    for (int mt = 0; mt < 4; mt++) {
        const int r0l = m_off + mt * 16 + gq;
#pragma unroll
        for (int nt = 0; nt < 8; nt++) {
            const int col = n0 + n_off + nt * 8 + tq * 2;
#pragma unroll
            for (int hrow = 0; hrow < 2; hrow++) {
                const int rl = r0l + hrow * 8;
                const int tok = s_tok[rl];
                const float p = s_p[rl];
                float* orow = out + ((size_t)b * T_ + tok) * C_ + col;
                atomicAdd(orow,     acc[mt][nt][2 * hrow + 0] * p);
                atomicAdd(orow + 1, acc[mt][nt][2 * hrow + 1] * p);
            }
        }
    }
}

// ======== launch (exactly 5 kernels) ========
extern "C" void kernel_launch(void* const* d_in, const int* in_sizes, int n_in,
                              void* d_out, int out_size) {
    const float* x  = (const float*)d_in[0];
    const float* gw = (const float*)d_in[1];
    const float* w1 = (const float*)d_in[2];
    const float* w2 = (const float*)d_in[3];
    float* out = (float*)d_out;

    cudaFuncSetAttribute(gemm1_mma, cudaFuncAttributeMaxDynamicSharedMemorySize, SMEM_BYTES_);
    cudaFuncSetAttribute(gemm2_mma, cudaFuncAttributeMaxDynamicSharedMemorySize, SMEM_BYTES_);

    gate_kernel<<<(B_ * T_) / 8, 256>>>(x, gw, (float4*)out);
    topk_kernel<<<G_, 1024>>>();

    const int WB = (E_ * C_ * H_) / (256 * 8);          // 16384
    prep_kernel<<<2 * WB + (G_ * CAP_) / 2, 256>>>(x, w1, w2);

    gemm1_mma<<<dim3(H_ / 256, CAP_ / 128, G_), 256, SMEM_BYTES_>>>();
    gemm2_mma<<<dim3(C_ / 256, CAP_ / 128, G_), 256, SMEM_BYTES_>>>(out);
}